// round 2
// baseline (speedup 1.0000x reference)
#include <cuda_runtime.h>
#include <math.h>
#include <stdint.h>

// SS2D: B=8 D=192 H=W=64 L=4096 N=16 R=6 K=4
#define Bb   8
#define Dd   192
#define Hh   64
#define Ww   64
#define Ll   4096
#define Nn   16
#define Rr   6
#define Kk   4
#define CDIM 38            // R + 2N
#define NCH  16            // L-chunks for parallel scan
#define LCH  (Ll/NCH)      // 256
#define TS   64            // steps staged per smem tile
#define XROW 40            // padded x_dbl smem row: dt[0..5], pad, B[8..23], C[24..39]

// ---- scratch (no allocations allowed -> device globals) ----
__device__ float g_xT  [(size_t)Bb*Dd*Ll];            // 24 MB  transposed planes
__device__ float g_xdbl[(size_t)Bb*Kk*CDIM*Ll];       // 19 MB  projections (scan order)
__device__ float g_hfin[(size_t)Bb*Kk*Dd*NCH*Nn];     // chunk-final local states
__device__ float g_S   [(size_t)Bb*Kk*Dd*NCH];        // chunk sum of dt
__device__ float g_hin [(size_t)Bb*Kk*Dd*NCH*Nn];     // chunk entry states
__device__ float g_ys  [(size_t)Bb*Kk*Ll*Dd];         // 96 MB  ys transposed [bk][l][d]

#define PROJ_SMEM ((CDIM*Dd + Dd*64)*4)               // 78336 B
#define SCAN_SMEM ((Dd*(TS+1) + TS*XROW)*4)           // 60160 B

// ---------------- transpose: xT[b,d, w*64+h] = x[b,d, h*64+w] ----------------
__global__ void ktranspose(const float* __restrict__ x) {
    __shared__ float t[32][33];
    int plane = blockIdx.z;                 // b*Dd + d
    int x0 = blockIdx.x * 32, y0 = blockIdx.y * 32;
    const float* src = x + (size_t)plane * Ll;
    float* dst = g_xT + (size_t)plane * Ll;
    int tx = threadIdx.x, ty = threadIdx.y; // 32x8
    #pragma unroll
    for (int i = 0; i < 32; i += 8)
        t[ty + i][tx] = src[(y0 + ty + i) * 64 + x0 + tx];
    __syncthreads();
    #pragma unroll
    for (int i = 0; i < 32; i += 8)
        dst[(x0 + ty + i) * 64 + y0 + tx] = t[tx][ty + i];
}

// ---------------- projection: x_dbl[b,k,c,l] = sum_d W[k,c,d] * xs[b,k,d,l] ----------------
__global__ void __launch_bounds__(256) kproj(const float* __restrict__ x,
                                             const float* __restrict__ W) {
    extern __shared__ float sm[];
    float* sW = sm;               // [38][192]
    float* sX = sm + CDIM * Dd;   // [192][64]
    int lt = blockIdx.x, k = blockIdx.y, b = blockIdx.z;
    int l0 = lt * 64;
    int tid = threadIdx.x;
    const float* src = ((k & 1) ? g_xT : x) + (size_t)b * Dd * Ll;
    bool rev = (k >= 2);

    for (int i = tid; i < CDIM * Dd; i += 256)
        sW[i] = W[(size_t)k * CDIM * Dd + i];
    for (int i = tid; i < Dd * 64; i += 256) {
        int dr = i >> 6, j = i & 63;
        int l = l0 + j;
        int pos = rev ? (Ll - 1 - l) : l;
        sX[i] = src[(size_t)dr * Ll + pos];
    }
    __syncthreads();

    // tiles: 19 c-pairs x 16 j-quads = 304 slots
    for (int t = tid; t < 19 * 16; t += 256) {
        int cp = t / 16, jq = t % 16;
        int c0 = cp * 2, j0 = jq * 4;
        float4 a0 = {0.f,0.f,0.f,0.f}, a1 = {0.f,0.f,0.f,0.f};
        const float* w0p = sW + c0 * Dd;
        const float* w1p = w0p + Dd;
        #pragma unroll 4
        for (int dd = 0; dd < Dd; dd++) {
            float4 xv = *(const float4*)(sX + dd * 64 + j0);
            float w0 = w0p[dd], w1 = w1p[dd];
            a0.x = fmaf(w0, xv.x, a0.x); a0.y = fmaf(w0, xv.y, a0.y);
            a0.z = fmaf(w0, xv.z, a0.z); a0.w = fmaf(w0, xv.w, a0.w);
            a1.x = fmaf(w1, xv.x, a1.x); a1.y = fmaf(w1, xv.y, a1.y);
            a1.z = fmaf(w1, xv.z, a1.z); a1.w = fmaf(w1, xv.w, a1.w);
        }
        float* o = g_xdbl + (((size_t)(b * Kk + k) * CDIM + c0) * Ll + l0 + j0);
        *(float4*)o = a0;
        *(float4*)(o + Ll) = a1;
    }
}

__device__ __forceinline__ float softplusf(float z) {
    return (z > 20.f) ? z : __logf(1.f + __expf(z));
}

// ---------------- chunked selective scan ----------------
// FIRST pass: local scan (h=0 entry), store chunk-final state + sum(dt).
// Second pass: real entry state from g_hin, emit y into g_ys[bk][l][d].
template <bool FIRST>
__global__ void __launch_bounds__(Dd, 3) kscan(const float* __restrict__ x,
                                               const float* __restrict__ dtw_g,
                                               const float* __restrict__ dtb_g,
                                               const float* __restrict__ A_logs,
                                               const float* __restrict__ Ds_g) {
    extern __shared__ float sm[];
    float* su = sm;                   // [192][65]
    float* sx = sm + Dd * (TS + 1);   // [64][40]

    int bid = blockIdx.x;
    int ch = bid % NCH, bk = bid / NCH;
    int b = bk / Kk, k = bk % Kk;
    int d = threadIdx.x;
    int kd = k * Dd + d;

    float A[Nn], dtw[Rr];
    #pragma unroll
    for (int n = 0; n < Nn; n++) A[n] = -__expf(A_logs[(size_t)kd * Nn + n]);
    #pragma unroll
    for (int r = 0; r < Rr; r++) dtw[r] = dtw_g[(size_t)kd * Rr + r];
    float dtb = dtb_g[kd];
    float Dskip = Ds_g[kd];

    const float* usrc = ((k & 1) ? g_xT : x) + (size_t)b * Dd * Ll;
    bool rev = (k >= 2);

    float h[Nn];
    size_t hb = ((size_t)(bk * Dd + d) * NCH + ch) * Nn;
    if (FIRST) {
        #pragma unroll
        for (int n = 0; n < Nn; n++) h[n] = 0.f;
    } else {
        #pragma unroll
        for (int n = 0; n < Nn; n++) h[n] = g_hin[hb + n];
    }
    float cumS = 0.f;

    const float* xdbl_b = g_xdbl + (size_t)bk * CDIM * Ll;
    float* ys_b = g_ys + (size_t)bk * Ll * Dd;
    int chbase = ch * LCH;

    for (int t0 = 0; t0 < LCH; t0 += TS) {
        int l0 = chbase + t0;
        // stage u tile [192][TS]
        for (int idx = d; idx < Dd * TS; idx += Dd) {
            int dr = idx >> 6, j = idx & 63;
            int l = l0 + j;
            int pos = rev ? (Ll - 1 - l) : l;
            su[dr * (TS + 1) + j] = usrc[(size_t)dr * Ll + pos];
        }
        // stage x_dbl tile, padded layout [j][40]
        for (int idx = d; idx < CDIM * TS; idx += Dd) {
            int c = idx >> 6, j = idx & 63;
            int cm = (c < Rr) ? c : c + 2;
            sx[j * XROW + cm] = xdbl_b[(size_t)c * Ll + l0 + j];
        }
        __syncthreads();

        #pragma unroll 1
        for (int j = 0; j < TS; j++) {
            const float* row = sx + j * XROW;
            float z = dtb;
            #pragma unroll
            for (int r = 0; r < Rr; r++) z = fmaf(dtw[r], row[r], z);
            float dt = softplusf(z);
            float uu = su[d * (TS + 1) + j];
            float du = dt * uu;
            float y = 0.f;
            const float4* B4 = (const float4*)(row + 8);
            const float4* C4 = (const float4*)(row + 24);
            #pragma unroll
            for (int q = 0; q < 4; q++) {
                float4 Bv = B4[q];
                float4 Cv = C4[q];
                int n = 4 * q;
                float dA;
                dA = __expf(dt * A[n + 0]); h[n + 0] = fmaf(h[n + 0], dA, du * Bv.x); y = fmaf(h[n + 0], Cv.x, y);
                dA = __expf(dt * A[n + 1]); h[n + 1] = fmaf(h[n + 1], dA, du * Bv.y); y = fmaf(h[n + 1], Cv.y, y);
                dA = __expf(dt * A[n + 2]); h[n + 2] = fmaf(h[n + 2], dA, du * Bv.z); y = fmaf(h[n + 2], Cv.z, y);
                dA = __expf(dt * A[n + 3]); h[n + 3] = fmaf(h[n + 3], dA, du * Bv.w); y = fmaf(h[n + 3], Cv.w, y);
            }
            if (FIRST) {
                cumS += dt;
            } else {
                y = fmaf(Dskip, uu, y);
                ys_b[(size_t)(l0 + j) * Dd + d] = y;
            }
        }
        __syncthreads();
    }

    if (FIRST) {
        #pragma unroll
        for (int n = 0; n < Nn; n++) g_hfin[hb + n] = h[n];
        g_S[(size_t)(bk * Dd + d) * NCH + ch] = cumS;
    }
}

// ---------------- sequential chunk-state combine (tiny) ----------------
__global__ void kcombine(const float* __restrict__ A_logs) {
    int thr = blockIdx.x * blockDim.x + threadIdx.x;   // (bk*Dd + d), 6144 total
    int d = thr % Dd;
    int bk = thr / Dd;
    int k = bk % Kk;
    float A[Nn];
    #pragma unroll
    for (int n = 0; n < Nn; n++) A[n] = -__expf(A_logs[(size_t)(k * Dd + d) * Nn + n]);
    float h[Nn];
    #pragma unroll
    for (int n = 0; n < Nn; n++) h[n] = 0.f;
    for (int c = 0; c < NCH; c++) {
        size_t base = ((size_t)thr * NCH + c) * Nn;
        #pragma unroll
        for (int n = 0; n < Nn; n++) g_hin[base + n] = h[n];
        float S = g_S[(size_t)thr * NCH + c];
        #pragma unroll
        for (int n = 0; n < Nn; n++) h[n] = fmaf(h[n], __expf(A[n] * S), g_hfin[base + n]);
    }
}

// ---------------- cross-merge + LayerNorm over D ----------------
__global__ void __launch_bounds__(Dd) kmerge(const float* __restrict__ nw,
                                             const float* __restrict__ nb,
                                             float* __restrict__ out) {
    int l = blockIdx.x, b = blockIdx.y, d = threadIdx.x;
    int lt = ((l & 63) << 6) | (l >> 6);   // (h,w) -> column-major scan position
    size_t pb = (size_t)b * Kk * Ll * Dd;
    float s = g_ys[pb + ((size_t)0 * Ll + l) * Dd + d]
            + g_ys[pb + ((size_t)2 * Ll + (Ll - 1 - l)) * Dd + d]
            + g_ys[pb + ((size_t)1 * Ll + lt) * Dd + d]
            + g_ys[pb + ((size_t)3 * Ll + (Ll - 1 - lt)) * Dd + d];

    __shared__ float rs[8];
    int w = d >> 5, lane = d & 31;
    float v = s;
    #pragma unroll
    for (int off = 16; off > 0; off >>= 1) v += __shfl_xor_sync(0xffffffffu, v, off);
    if (lane == 0) rs[w] = v;
    __syncthreads();
    if (d == 0) {
        float t = 0.f;
        #pragma unroll
        for (int i = 0; i < 6; i++) t += rs[i];
        rs[6] = t * (1.f / Dd);
    }
    __syncthreads();
    float mu = rs[6];
    float dv = s - mu;
    v = dv * dv;
    #pragma unroll
    for (int off = 16; off > 0; off >>= 1) v += __shfl_xor_sync(0xffffffffu, v, off);
    if (lane == 0) rs[w] = v;
    __syncthreads();
    if (d == 0) {
        float t = 0.f;
        #pragma unroll
        for (int i = 0; i < 6; i++) t += rs[i];
        rs[7] = t * (1.f / Dd);
    }
    __syncthreads();
    float var = rs[7];
    out[((size_t)b * Ll + l) * Dd + d] = dv * rsqrtf(var + 1e-5f) * nw[d] + nb[d];
}

extern "C" void kernel_launch(void* const* d_in, const int* in_sizes, int n_in,
                              void* d_out, int out_size) {
    const float* x    = (const float*)d_in[0];
    const float* xpw  = (const float*)d_in[1];
    const float* dtw  = (const float*)d_in[2];
    const float* dtb  = (const float*)d_in[3];
    const float* alog = (const float*)d_in[4];
    const float* Ds   = (const float*)d_in[5];
    const float* nw   = (const float*)d_in[6];
    const float* nb   = (const float*)d_in[7];
    float* out = (float*)d_out;

    cudaFuncSetAttribute(kproj, cudaFuncAttributeMaxDynamicSharedMemorySize, PROJ_SMEM);
    cudaFuncSetAttribute(kscan<true>, cudaFuncAttributeMaxDynamicSharedMemorySize, SCAN_SMEM);
    cudaFuncSetAttribute(kscan<false>, cudaFuncAttributeMaxDynamicSharedMemorySize, SCAN_SMEM);

    ktranspose<<<dim3(2, 2, Bb * Dd), dim3(32, 8)>>>(x);
    kproj<<<dim3(Ll / 64, Kk, Bb), 256, PROJ_SMEM>>>(x, xpw);
    kscan<true><<<Bb * Kk * NCH, Dd, SCAN_SMEM>>>(x, dtw, dtb, alog, Ds);
    kcombine<<<(Bb * Kk * Dd) / Dd, Dd>>>(alog);
    kscan<false><<<Bb * Kk * NCH, Dd, SCAN_SMEM>>>(x, dtw, dtb, alog, Ds);
    kmerge<<<dim3(Ll, Bb), Dd>>>(nw, nb, out);
}

// round 5
// speedup vs baseline: 1.8149x; 1.8149x over previous
#include <cuda_runtime.h>
#include <math.h>
#include <stdint.h>

// SS2D: B=8 D=192 H=W=64 L=4096 N=16 R=6 K=4
#define Bb   8
#define Dd   192
#define Hh   64
#define Ww   64
#define Ll   4096
#define Nn   16
#define Rr   6
#define Kk   4
#define CDIM 38            // R + 2N
#define NCH  16            // L-chunks for parallel scan
#define LCH  (Ll/NCH)      // 256
#define TS   32            // steps staged per smem tile
#define XROW 40            // padded x_dbl smem row: dt[0..5], pad, B[8..23], C[24..39]

// ---- scratch (no allocations allowed -> device globals) ----
__device__ float g_xT  [(size_t)Bb*Dd*Ll];            // 24 MB  transposed planes
__device__ float g_xdbl[(size_t)Bb*Kk*CDIM*Ll];       // 19 MB  projections (scan order)
__device__ float g_hfin[(size_t)Bb*Kk*NCH*Dd*Nn];     // [bk][ch][d][n] chunk-final local states
__device__ float g_S   [(size_t)Bb*Kk*NCH*Dd];        // [bk][ch][d]    chunk sum of dt
__device__ float g_hin [(size_t)Bb*Kk*NCH*Dd*Nn];     // [bk][ch][d][n] chunk entry states
__device__ float g_ys  [(size_t)Bb*Kk*Ll*Dd];         // 96 MB  ys transposed [bk][l][d]

#define PROJ_SMEM ((CDIM*Dd + Dd*64)*4)               // 78336 B
#define SCAN_SMEM ((Dd*(TS+1) + TS*XROW)*4)           // 30464 B

// ---------------- transpose: xT[b,d, w*64+h] = x[b,d, h*64+w] ----------------
__global__ void ktranspose(const float* __restrict__ x) {
    __shared__ float t[32][33];
    int plane = blockIdx.z;                 // b*Dd + d
    int x0 = blockIdx.x * 32, y0 = blockIdx.y * 32;
    const float* src = x + (size_t)plane * Ll;
    float* dst = g_xT + (size_t)plane * Ll;
    int tx = threadIdx.x, ty = threadIdx.y; // 32x8
    #pragma unroll
    for (int i = 0; i < 32; i += 8)
        t[ty + i][tx] = src[(y0 + ty + i) * 64 + x0 + tx];
    __syncthreads();
    #pragma unroll
    for (int i = 0; i < 32; i += 8)
        dst[(x0 + ty + i) * 64 + y0 + tx] = t[tx][ty + i];
}

// ---------------- projection: x_dbl[b,k,c,l] = sum_d W[k,c,d] * xs[b,k,d,l] ----------------
__global__ void __launch_bounds__(256) kproj(const float* __restrict__ x,
                                             const float* __restrict__ W) {
    extern __shared__ float sm[];
    float* sW = sm;               // [38][192]
    float* sX = sm + CDIM * Dd;   // [192][64]
    int lt = blockIdx.x, k = blockIdx.y, b = blockIdx.z;
    int l0 = lt * 64;
    int tid = threadIdx.x;
    const float* src = ((k & 1) ? g_xT : x) + (size_t)b * Dd * Ll;
    bool rev = (k >= 2);

    for (int i = tid; i < CDIM * Dd; i += 256)
        sW[i] = W[(size_t)k * CDIM * Dd + i];
    for (int i = tid; i < Dd * 64; i += 256) {
        int dr = i >> 6, j = i & 63;
        int l = l0 + j;
        int pos = rev ? (Ll - 1 - l) : l;
        sX[i] = src[(size_t)dr * Ll + pos];
    }
    __syncthreads();

    // tiles: 19 c-pairs x 16 j-quads = 304 slots
    for (int t = tid; t < 19 * 16; t += 256) {
        int cp = t / 16, jq = t % 16;
        int c0 = cp * 2, j0 = jq * 4;
        float4 a0 = {0.f,0.f,0.f,0.f}, a1 = {0.f,0.f,0.f,0.f};
        const float* w0p = sW + c0 * Dd;
        const float* w1p = w0p + Dd;
        #pragma unroll 4
        for (int dd = 0; dd < Dd; dd++) {
            float4 xv = *(const float4*)(sX + dd * 64 + j0);
            float w0 = w0p[dd], w1 = w1p[dd];
            a0.x = fmaf(w0, xv.x, a0.x); a0.y = fmaf(w0, xv.y, a0.y);
            a0.z = fmaf(w0, xv.z, a0.z); a0.w = fmaf(w0, xv.w, a0.w);
            a1.x = fmaf(w1, xv.x, a1.x); a1.y = fmaf(w1, xv.y, a1.y);
            a1.z = fmaf(w1, xv.z, a1.z); a1.w = fmaf(w1, xv.w, a1.w);
        }
        float* o = g_xdbl + (((size_t)(b * Kk + k) * CDIM + c0) * Ll + l0 + j0);
        *(float4*)o = a0;
        *(float4*)(o + Ll) = a1;
    }
}

__device__ __forceinline__ float softplusf(float z) {
    return (z > 20.f) ? z : __logf(1.f + __expf(z));
}

// ---------------- chunked selective scan ----------------
// FIRST pass: local scan (h=0 entry), store chunk-final state + sum(dt).
// Second pass: real entry state from g_hin, emit y into g_ys[bk][l][d].
template <bool FIRST>
__global__ void __launch_bounds__(Dd, 4) kscan(const float* __restrict__ x,
                                               const float* __restrict__ dtw_g,
                                               const float* __restrict__ dtb_g,
                                               const float* __restrict__ A_logs,
                                               const float* __restrict__ Ds_g) {
    extern __shared__ float sm[];
    float* su = sm;                   // [192][TS+1]
    float* sx = sm + Dd * (TS + 1);   // [TS][40]

    int bid = blockIdx.x;
    int ch = bid % NCH, bk = bid / NCH;
    int b = bk / Kk, k = bk % Kk;
    int d = threadIdx.x;
    int kd = k * Dd + d;

    float A[Nn], dtw[Rr];
    #pragma unroll
    for (int n = 0; n < Nn; n++) A[n] = -__expf(A_logs[(size_t)kd * Nn + n]);
    #pragma unroll
    for (int r = 0; r < Rr; r++) dtw[r] = dtw_g[(size_t)kd * Rr + r];
    float dtb = dtb_g[kd];
    float Dskip = Ds_g[kd];

    const float* usrc = ((k & 1) ? g_xT : x) + (size_t)b * Dd * Ll;
    bool rev = (k >= 2);

    float h[Nn];
    // [bk][ch][d][n] layout -> coalesced in kcombine and here
    size_t hb = ((size_t)(bk * NCH + ch) * Dd + d) * Nn;
    if (FIRST) {
        #pragma unroll
        for (int n = 0; n < Nn; n++) h[n] = 0.f;
    } else {
        const float4* hi4 = (const float4*)(g_hin + hb);
        #pragma unroll
        for (int q = 0; q < 4; q++) {
            float4 v = hi4[q];
            h[4*q+0] = v.x; h[4*q+1] = v.y; h[4*q+2] = v.z; h[4*q+3] = v.w;
        }
    }
    float cumS = 0.f;

    const float* xdbl_b = g_xdbl + (size_t)bk * CDIM * Ll;
    float* ys_b = g_ys + (size_t)bk * Ll * Dd;
    int chbase = ch * LCH;

    for (int t0 = 0; t0 < LCH; t0 += TS) {
        int l0 = chbase + t0;
        // stage u tile [192][TS]
        for (int idx = d; idx < Dd * TS; idx += Dd) {
            int dr = idx >> 5, j = idx & (TS - 1);
            int l = l0 + j;
            int pos = rev ? (Ll - 1 - l) : l;
            su[dr * (TS + 1) + j] = usrc[(size_t)dr * Ll + pos];
        }
        // stage x_dbl tile, padded layout [j][40]
        for (int idx = d; idx < CDIM * TS; idx += Dd) {
            int c = idx >> 5, j = idx & (TS - 1);
            int cm = (c < Rr) ? c : c + 2;
            sx[j * XROW + cm] = xdbl_b[(size_t)c * Ll + l0 + j];
        }
        __syncthreads();

        #pragma unroll 1
        for (int j = 0; j < TS; j++) {
            const float* row = sx + j * XROW;
            float z = dtb;
            #pragma unroll
            for (int r = 0; r < Rr; r++) z = fmaf(dtw[r], row[r], z);
            float dt = softplusf(z);
            float uu = su[d * (TS + 1) + j];
            float du = dt * uu;
            const float4* B4 = (const float4*)(row + 8);
            if constexpr (FIRST) {
                #pragma unroll
                for (int q = 0; q < 4; q++) {
                    float4 Bv = B4[q];
                    int n = 4 * q;
                    h[n + 0] = fmaf(h[n + 0], __expf(dt * A[n + 0]), du * Bv.x);
                    h[n + 1] = fmaf(h[n + 1], __expf(dt * A[n + 1]), du * Bv.y);
                    h[n + 2] = fmaf(h[n + 2], __expf(dt * A[n + 2]), du * Bv.z);
                    h[n + 3] = fmaf(h[n + 3], __expf(dt * A[n + 3]), du * Bv.w);
                }
                cumS += dt;
            } else {
                float y = 0.f;
                const float4* C4 = (const float4*)(row + 24);
                #pragma unroll
                for (int q = 0; q < 4; q++) {
                    float4 Bv = B4[q];
                    float4 Cv = C4[q];
                    int n = 4 * q;
                    float dA;
                    dA = __expf(dt * A[n + 0]); h[n + 0] = fmaf(h[n + 0], dA, du * Bv.x); y = fmaf(h[n + 0], Cv.x, y);
                    dA = __expf(dt * A[n + 1]); h[n + 1] = fmaf(h[n + 1], dA, du * Bv.y); y = fmaf(h[n + 1], Cv.y, y);
                    dA = __expf(dt * A[n + 2]); h[n + 2] = fmaf(h[n + 2], dA, du * Bv.z); y = fmaf(h[n + 2], Cv.z, y);
                    dA = __expf(dt * A[n + 3]); h[n + 3] = fmaf(h[n + 3], dA, du * Bv.w); y = fmaf(h[n + 3], Cv.w, y);
                }
                y = fmaf(Dskip, uu, y);
                ys_b[(size_t)(l0 + j) * Dd + d] = y;
            }
        }
        __syncthreads();
    }

    if constexpr (FIRST) {
        float4* hf4 = (float4*)(g_hfin + hb);
        #pragma unroll
        for (int q = 0; q < 4; q++)
            hf4[q] = make_float4(h[4*q+0], h[4*q+1], h[4*q+2], h[4*q+3]);
        g_S[(size_t)(bk * NCH + ch) * Dd + d] = cumS;
    }
}

// ---------------- parallel chunk-state combine ----------------
// one thread per (bk, d, n): serial over NCH chunks, coalesced accesses.
__global__ void __launch_bounds__(256) kcombine(const float* __restrict__ A_logs) {
    int t = blockIdx.x * blockDim.x + threadIdx.x;     // bk*Dd*Nn + d*Nn + n
    int n = t & (Nn - 1);
    int bk = t / (Dd * Nn);
    int d = (t / Nn) % Dd;
    int k = bk % Kk;
    float A = -__expf(A_logs[(size_t)(k * Dd + d) * Nn + n]);
    float h = 0.f;
    size_t dnoff = (size_t)(t % (Dd * Nn));
    #pragma unroll 1
    for (int c = 0; c < NCH; c++) {
        size_t base = ((size_t)(bk * NCH + c)) * Dd * Nn + dnoff;
        g_hin[base] = h;
        float S = g_S[(size_t)(bk * NCH + c) * Dd + d];
        h = fmaf(h, __expf(A * S), g_hfin[base]);
    }
}

// ---------------- cross-merge + LayerNorm over D ----------------
__global__ void __launch_bounds__(Dd) kmerge(const float* __restrict__ nw,
                                             const float* __restrict__ nb,
                                             float* __restrict__ out) {
    int l = blockIdx.x, b = blockIdx.y, d = threadIdx.x;
    int lt = ((l & 63) << 6) | (l >> 6);   // (h,w) -> column-major scan position
    size_t pb = (size_t)b * Kk * Ll * Dd;
    float s = g_ys[pb + ((size_t)0 * Ll + l) * Dd + d]
            + g_ys[pb + ((size_t)2 * Ll + (Ll - 1 - l)) * Dd + d]
            + g_ys[pb + ((size_t)1 * Ll + lt) * Dd + d]
            + g_ys[pb + ((size_t)3 * Ll + (Ll - 1 - lt)) * Dd + d];

    __shared__ float rs[8];
    int w = d >> 5, lane = d & 31;
    float v = s;
    #pragma unroll
    for (int off = 16; off > 0; off >>= 1) v += __shfl_xor_sync(0xffffffffu, v, off);
    if (lane == 0) rs[w] = v;
    __syncthreads();
    if (d == 0) {
        float t = 0.f;
        #pragma unroll
        for (int i = 0; i < 6; i++) t += rs[i];
        rs[6] = t * (1.f / Dd);
    }
    __syncthreads();
    float mu = rs[6];
    float dv = s - mu;
    v = dv * dv;
    #pragma unroll
    for (int off = 16; off > 0; off >>= 1) v += __shfl_xor_sync(0xffffffffu, v, off);
    if (lane == 0) rs[w] = v;
    __syncthreads();
    if (d == 0) {
        float t = 0.f;
        #pragma unroll
        for (int i = 0; i < 6; i++) t += rs[i];
        rs[7] = t * (1.f / Dd);
    }
    __syncthreads();
    float var = rs[7];
    out[((size_t)b * Ll + l) * Dd + d] = dv * rsqrtf(var + 1e-5f) * nw[d] + nb[d];
}

extern "C" void kernel_launch(void* const* d_in, const int* in_sizes, int n_in,
                              void* d_out, int out_size) {
    const float* x    = (const float*)d_in[0];
    const float* xpw  = (const float*)d_in[1];
    const float* dtw  = (const float*)d_in[2];
    const float* dtb  = (const float*)d_in[3];
    const float* alog = (const float*)d_in[4];
    const float* Ds   = (const float*)d_in[5];
    const float* nw   = (const float*)d_in[6];
    const float* nb   = (const float*)d_in[7];
    float* out = (float*)d_out;

    cudaFuncSetAttribute(kproj, cudaFuncAttributeMaxDynamicSharedMemorySize, PROJ_SMEM);
    cudaFuncSetAttribute(kscan<true>, cudaFuncAttributeMaxDynamicSharedMemorySize, SCAN_SMEM);
    cudaFuncSetAttribute(kscan<false>, cudaFuncAttributeMaxDynamicSharedMemorySize, SCAN_SMEM);

    ktranspose<<<dim3(2, 2, Bb * Dd), dim3(32, 8)>>>(x);
    kproj<<<dim3(Ll / 64, Kk, Bb), 256, PROJ_SMEM>>>(x, xpw);
    kscan<true><<<Bb * Kk * NCH, Dd, SCAN_SMEM>>>(x, dtw, dtb, alog, Ds);
    kcombine<<<(Bb * Kk * Dd * Nn) / 256, 256>>>(alog);
    kscan<false><<<Bb * Kk * NCH, Dd, SCAN_SMEM>>>(x, dtw, dtb, alog, Ds);
    kmerge<<<dim3(Ll, Bb), Dd>>>(nw, nb, out);
}